// round 3
// baseline (speedup 1.0000x reference)
#include <cuda_runtime.h>

#define NIMG 2
#define CC   10
#define HH   30
#define WW   30
#define DD   11
#define PADR 4
#define FULL 0xFFFFFFFFu

__device__ unsigned char g_clsmap[NIMG * HH * WW];

__global__ __launch_bounds__(128) void decode_kernel(const float* __restrict__ x) {
    int t = blockIdx.x * 128 + threadIdx.x;
    if (t >= NIMG * HH * WW) return;
    int n = t / (HH * WW);
    int p = t % (HH * WW);
    const float* px = x + (long)n * CC * HH * WW + p;
    int cls = 0;
    #pragma unroll
    for (int c = 0; c < CC; c++)
        if (px[c * HH * WW] > 0.5f) cls = c;
    g_clsmap[t] = (unsigned char)cls;
}

__device__ __forceinline__ float wsum(float v) {
    #pragma unroll
    for (int o = 16; o; o >>= 1) v += __shfl_xor_sync(FULL, v, o);
    return v;
}
__device__ __forceinline__ float wmax(float v) {
    #pragma unroll
    for (int o = 16; o; o >>= 1) v = fmaxf(v, __shfl_xor_sync(FULL, v, o));
    return v;
}

__global__ __launch_bounds__(256) void pve_kernel(
    const float* __restrict__ w_in,   // [33,11]
    const float* __restrict__ w_out,  // [11,11]
    const float* __restrict__ w_ff1,  // [1,11]
    const float* __restrict__ w_ff2,  // [11,1]
    const float* __restrict__ ln1_g,  // [11]
    const float* __restrict__ ln2_g,  // [11]
    float* __restrict__ out)          // [1800,10,100]
{
    const int lane = threadIdx.x & 31;
    const int b    = blockIdx.x * 8 + (threadIdx.x >> 5);   // pixel id, 225*8=1800
    const int n    = b / (HH * WW);
    const int rem  = b % (HH * WW);
    const int pi   = rem / WW, pj = rem % WW;

    const bool haspad = (pi < PADR) | (pi > HH - 1 - PADR) |
                        (pj < PADR) | (pj > WW - 1 - PADR);   // warp-uniform

    // ── build packed class word: lane j (<25) owns slots l=4j..4j+3 ──
    unsigned int word = 0xFFFFFFFFu;
    if (lane < 25) {
        word = 0;
        #pragma unroll
        for (int e = 0; e < 4; e++) {
            int l = 4 * lane + e;
            int mh = l / 10, mw = l % 10;
            unsigned int cls = 255;
            if (mh < 9 && mw < 9) {
                int si = pi + mh - PADR, sj = pj + mw - PADR;
                cls = 10;
                if (si >= 0 && si < HH && sj >= 0 && sj < WW)
                    cls = g_clsmap[(n * HH + si) * WW + sj];
            }
            word |= cls << (8 * e);
        }
    }

    float pv = 0.f;   // padvec[lane] for lane<10 on border warps

    if (haspad) {
        // ── class histogram: lane d counts class d over 25 words ──
        unsigned int target = lane;
        int cnt = 0;
        #pragma unroll
        for (int j = 0; j < 25; j++) {
            unsigned int w = __shfl_sync(FULL, word, j);
            cnt += ((w & 0xFF) == target);
            cnt += (((w >> 8) & 0xFF) == target);
            cnt += (((w >> 16) & 0xFF) == target);
            cnt += ((w >> 24) == target);
        }
        float fcnt = (float)cnt;

        // ── attention for single query class 10; lane d owns dim d ──
        const int d = lane;
        float ao = 0.f;
        if (d < DD) {
            float q10 = w_in[d * DD + 10];
            float num = 0.f, den = 0.f;
            #pragma unroll
            for (int c = 0; c < DD; c++) {
                float hc = __shfl_sync(FULL, fcnt, c);
                float k = w_in[(DD + d) * DD + c];
                float v = w_in[(2 * DD + d) * DD + c];
                float e = __expf(q10 * k) * hc;
                den += e;
                num += e * v;
            }
            ao = num / den;
        } else {
            // lanes >=11 still participate in the shfls below
            #pragma unroll
            for (int c = 0; c < DD; c++) (void)__shfl_sync(FULL, fcnt, c);
        }

        // ── svec = e_10 + ao @ w_out^T ──
        float s = (d == 10) ? 1.0f : 0.0f;
        #pragma unroll
        for (int dd2 = 0; dd2 < DD; dd2++) {
            float a = __shfl_sync(FULL, ao, dd2);
            if (d < DD) s += a * w_out[d * DD + dd2];
        }
        float sv = (d < DD) ? s : 0.f;

        // ── LN1 ──
        float m = wsum(sv) * (1.0f / 11.0f);
        float dv = (d < DD) ? (sv - m) : 0.f;
        float var = wsum(dv * dv) * (1.0f / 11.0f);
        float inv = rsqrtf(var + 1e-5f);
        float h1 = (d < DD) ? dv * inv * ln1_g[d] : 0.f;

        // ── FF ──
        float t = wsum((d < DD) ? h1 * w_ff1[d] : 0.f);
        t = fmaxf(t, 0.f);
        float h2 = (d < DD) ? h1 + t * w_ff2[d] : 0.f;

        // ── LN2 ──
        float m2 = wsum(h2) * (1.0f / 11.0f);
        float dv2 = (d < DD) ? (h2 - m2) : 0.f;
        float var2 = wsum(dv2 * dv2) * (1.0f / 11.0f);
        float inv2 = rsqrtf(var2 + 1e-5f);
        float hh = (d < DD) ? dv2 * inv2 * ln2_g[d] : 0.f;

        // ── softmax over classes 0..9 ──
        float z = (d < CC) ? hh : -1e30f;
        float mx = wmax(z);
        float ex = (d < CC) ? __expf(z - mx) : 0.f;
        float se = wsum(ex);
        pv = ex / se;   // lane c holds padvec[c] (c<10), 0 elsewhere
    }

    // ── scatter 250 float4 (q = c*25 + j), coalesced ──
    float4* o4 = reinterpret_cast<float4*>(out + (long)b * 1000);
    #pragma unroll
    for (int it = 0; it < 8; it++) {
        int q = lane + it * 32;                 // < 256
        int c = q / 25;                         // <= 10
        int j = q - c * 25;
        unsigned int w  = __shfl_sync(FULL, word, j);
        float        pc = __shfl_sync(FULL, pv, c);
        if (q < 250) {
            float4 r;
            float* rp = &r.x;
            #pragma unroll
            for (int e = 0; e < 4; e++) {
                unsigned int cls = (w >> (8 * e)) & 0xFF;
                float v = 0.f;
                if (cls != 255) v = (cls == 10) ? pc : (cls == (unsigned)c ? 1.0f : 0.0f);
                rp[e] = v;
            }
            o4[q] = r;
        }
    }
}

extern "C" void kernel_launch(void* const* d_in, const int* in_sizes, int n_in,
                              void* d_out, int out_size) {
    const float* x     = (const float*)d_in[0];
    const float* w_in  = (const float*)d_in[1];
    const float* w_out = (const float*)d_in[2];
    const float* w_ff1 = (const float*)d_in[3];
    const float* w_ff2 = (const float*)d_in[4];
    const float* ln1_g = (const float*)d_in[5];
    const float* ln2_g = (const float*)d_in[6];

    decode_kernel<<<(NIMG * HH * WW + 127) / 128, 128>>>(x);
    pve_kernel<<<225, 256>>>(w_in, w_out, w_ff1, w_ff2, ln1_g, ln2_g, (float*)d_out);
}

// round 4
// speedup vs baseline: 2.7036x; 2.7036x over previous
#include <cuda_runtime.h>

#define CC   10
#define HH   30
#define WW   30
#define DD   11
#define FULL 0xFFFFFFFFu

__device__ __forceinline__ float rsum16(float v) {
    #pragma unroll
    for (int o = 1; o < 16; o <<= 1) v += __shfl_xor_sync(FULL, v, o);
    return v;
}
__device__ __forceinline__ float rmax16(float v) {
    #pragma unroll
    for (int o = 1; o < 16; o <<= 1) v = fmaxf(v, __shfl_xor_sync(FULL, v, o));
    return v;
}

__global__ __launch_bounds__(128) void pve_fused(
    const float* __restrict__ x,      // [2,10,30,30] one-hot
    const float* __restrict__ w_in,   // [33,11]
    const float* __restrict__ w_out,  // [11,11]
    const float* __restrict__ w_ff1,  // [1,11]
    const float* __restrict__ w_ff2,  // [11,1]
    const float* __restrict__ ln1_g,  // [11]
    const float* __restrict__ ln2_g,  // [11]
    float* __restrict__ out)          // [1800,10,100]
{
    __shared__ unsigned char ctile[10][10]; // class per region pixel (10 = img pad)
    __shared__ unsigned int  wtab[4][25];   // per-pixel packed slot classes
    __shared__ float         pvs[4][10];    // per-pixel padding softmax vector

    const int tid  = threadIdx.x;
    const int lane = tid & 31;
    const int w    = tid >> 5;

    const int blk = blockIdx.x;           // 450 blocks: 2 imgs x 15 x 15 tiles
    const int n   = blk / 225;
    const int t   = blk % 225;
    const int pi0 = (t / 15) * 2;
    const int pj0 = (t % 15) * 2;

    // ── decode shared 10x10 class region (one-hot -> class via dot) ──
    if (tid < 100) {
        int rr = tid / 10, cc2 = tid % 10;
        int si = pi0 - 4 + rr, sj = pj0 - 4 + cc2;
        int cls = 10;
        if (si >= 0 && si < HH && sj >= 0 && sj < WW) {
            const float* px = x + ((long)n * CC * HH + si) * WW + sj;
            float acc = 0.f;
            #pragma unroll
            for (int c = 1; c < CC; c++) acc += (float)c * px[c * HH * WW];
            cls = __float2int_rn(acc);
        }
        ctile[rr][cc2] = (unsigned char)cls;
    }
    __syncthreads();

    // warp w owns pixel (pi0+dpi, pj0+dpj)
    const int dpi = w >> 1, dpj = w & 1;
    const int pi = pi0 + dpi, pj = pj0 + dpj;
    const int b  = (n * HH + pi) * WW + pj;
    const bool haspad = (pi < 4) | (pi > HH - 5) | (pj < 4) | (pj > WW - 5);

    // packed class word: lane j (<25) owns slots l=4j..4j+3 (l = mh*10+mw)
    unsigned int word = 0xFFFFFFFFu;
    if (lane < 25) {
        word = 0;
        #pragma unroll
        for (int e = 0; e < 4; e++) {
            int l  = 4 * lane + e;
            int mh = l / 10, mw = l % 10;
            unsigned int cls = 255;
            if (mh < 9 && mw < 9) cls = ctile[dpi + mh][dpj + mw];
            word |= cls << (8 * e);
        }
        wtab[w][lane] = word;
    }
    if (lane < CC) pvs[w][lane] = 0.f;

    if (haspad) {
        const int d = lane;
        float kk[DD], vv[DD], q10 = 0.f;
        if (d < DD) {
            q10 = w_in[d * DD + 10];
            #pragma unroll
            for (int c = 0; c < DD; c++) {
                kk[c] = w_in[(DD + d) * DD + c];
                vv[c] = w_in[(2 * DD + d) * DD + c];
            }
        }
        // fused histogram (vcmp+popc+redux) + attention accumulation
        float num = 0.f, den = 0.f;
        #pragma unroll
        for (int c = 0; c < DD; c++) {
            unsigned int eq  = __vcmpeq4(word, c * 0x01010101u);
            int          cnt = __popc(eq) >> 3;
            int          hc  = __reduce_add_sync(FULL, cnt);
            if (d < DD) {
                float e = __expf(q10 * kk[c]) * (float)hc;
                den += e;
                num += e * vv[c];
            }
        }
        float ao = (d < DD) ? num / den : 0.f;

        // svec = e_10 + ao @ w_out^T
        float acc = (d == 10) ? 1.f : 0.f;
        #pragma unroll
        for (int c = 0; c < DD; c++) {
            float a = __shfl_sync(FULL, ao, c);
            if (d < DD) acc += a * w_out[d * DD + c];
        }
        float sv = (d < DD) ? acc : 0.f;

        // LN1 (mean + E[x^2], independent reduction chains)
        float s1 = rsum16(sv);
        float s2 = rsum16(sv * sv);
        float m   = s1 * (1.f / 11.f);
        float var = fmaxf(s2 * (1.f / 11.f) - m * m, 0.f);
        float inv = rsqrtf(var + 1e-5f);
        float h1  = (d < DD) ? (sv - m) * inv * ln1_g[d] : 0.f;

        // FF
        float tt = rsum16((d < DD) ? h1 * w_ff1[d] : 0.f);
        tt = fmaxf(tt, 0.f);
        float h2 = (d < DD) ? h1 + tt * w_ff2[d] : 0.f;

        // LN2
        float t1 = rsum16(h2);
        float t2 = rsum16(h2 * h2);
        float m2   = t1 * (1.f / 11.f);
        float var2 = fmaxf(t2 * (1.f / 11.f) - m2 * m2, 0.f);
        float inv2 = rsqrtf(var2 + 1e-5f);
        float hhv  = (d < DD) ? (h2 - m2) * inv2 * ln2_g[d] : 0.f;

        // softmax over classes 0..9
        float z  = (d < CC) ? hhv : -1e30f;
        float mx = rmax16(z);
        float ex = (d < CC) ? __expf(z - mx) : 0.f;
        float se = rsum16(ex);
        if (d < CC) pvs[w][d] = ex / se;
    }
    __syncwarp();

    // ── scatter 250 float4 for this pixel, coalesced (q = c*25 + j) ──
    float4* o4 = reinterpret_cast<float4*>(out + (long)b * 1000);
    #pragma unroll
    for (int it = 0; it < 8; it++) {
        int q = lane + it * 32;
        if (q < 250) {
            int c = q / 25;                 // <= 9
            int j = q - c * 25;
            unsigned int wd = wtab[w][j];
            float        pc = pvs[w][c];
            float4 r;
            float* rp = &r.x;
            #pragma unroll
            for (int e = 0; e < 4; e++) {
                unsigned int cls = (wd >> (8 * e)) & 0xFF;
                // cls==255 (masked) fails both compares -> 0
                rp[e] = (cls == 10u) ? pc : ((cls == (unsigned)c) ? 1.0f : 0.0f);
            }
            o4[q] = r;
        }
    }
}

extern "C" void kernel_launch(void* const* d_in, const int* in_sizes, int n_in,
                              void* d_out, int out_size) {
    const float* x     = (const float*)d_in[0];
    const float* w_in  = (const float*)d_in[1];
    const float* w_out = (const float*)d_in[2];
    const float* w_ff1 = (const float*)d_in[3];
    const float* w_ff2 = (const float*)d_in[4];
    const float* ln1_g = (const float*)d_in[5];
    const float* ln2_g = (const float*)d_in[6];

    pve_fused<<<450, 128>>>(x, w_in, w_out, w_ff1, w_ff2, ln1_g, ln2_g,
                            (float*)d_out);
}